// round 4
// baseline (speedup 1.0000x reference)
#include <cuda_runtime.h>
#include <cuda_bf16.h>

// Problem constants (fixed by the dataset)
#define NN 50000
#define EE 800000
#define ET (EE + NN)   // edges + self loops
#define GG 64
#define FIN 128
#define MAXD 256

// ---------------- scratch (device globals; no allocation allowed) ----------
__device__ float    g_bufA[(size_t)NN * MAXD];
__device__ float    g_bufB[(size_t)NN * MAXD];
__device__ float    g_bufC[(size_t)NN * MAXD];
__device__ float    g_edge[ET];
__device__ float    g_ssrc[NN];
__device__ float    g_sdst[NN];
__device__ unsigned g_mu[NN];
__device__ float    g_denom[NN];
__device__ unsigned g_x1u[GG * MAXD];
__device__ float    g_x2[GG * MAXD];
__device__ float    g_x3[GG * MAXD];
__device__ float    g_cnt[GG];
__device__ float    g_z[GG * 512];
__device__ float    g_t1[GG * MAXD];
__device__ float    g_t2[GG * MAXD];
__device__ float    g_gate[GG * 64];

// monotone float <-> uint mapping for atomicMax on signed floats
__device__ __forceinline__ unsigned f2u_ord(float f) {
    unsigned u = __float_as_uint(f);
    return (u & 0x80000000u) ? ~u : (u | 0x80000000u);
}
__device__ __forceinline__ float u2f_ord(unsigned u) {
    return __uint_as_float((u & 0x80000000u) ? (u & 0x7FFFFFFFu) : ~u);
}

// ---------------- tiled fp32 GEMM: C[M,Nd] = A[M,K] @ B[K,Nd] --------------
// BM=BN=64, BK=16, 16x16 threads, 4x4 per thread. K % 16 == 0, Nd % 64 == 0.
__global__ void gemm_k(const float* __restrict__ A, const float* __restrict__ B,
                       float* __restrict__ C, int M, int K, int Nd) {
    __shared__ float As[16][65];
    __shared__ float Bs[16][64];
    int tl = threadIdx.y * 16 + threadIdx.x;
    int brow = blockIdx.x * 64, bcol = blockIdx.y * 64;
    float acc[4][4] = {};
    for (int k0 = 0; k0 < K; k0 += 16) {
        int r = tl >> 2, c = (tl & 3) * 4;
        float4 av = make_float4(0.f, 0.f, 0.f, 0.f);
        if (brow + r < M)
            av = *(const float4*)&A[(size_t)(brow + r) * K + k0 + c];
        As[c + 0][r] = av.x; As[c + 1][r] = av.y;
        As[c + 2][r] = av.z; As[c + 3][r] = av.w;
        int r2 = tl >> 4, c2 = (tl & 15) * 4;
        *(float4*)&Bs[r2][c2] = *(const float4*)&B[(size_t)(k0 + r2) * Nd + bcol + c2];
        __syncthreads();
        #pragma unroll
        for (int k = 0; k < 16; k++) {
            float a[4], b[4];
            #pragma unroll
            for (int i = 0; i < 4; i++) a[i] = As[k][threadIdx.y * 4 + i];
            #pragma unroll
            for (int j = 0; j < 4; j++) b[j] = Bs[k][threadIdx.x * 4 + j];
            #pragma unroll
            for (int i = 0; i < 4; i++)
                #pragma unroll
                for (int j = 0; j < 4; j++) acc[i][j] += a[i] * b[j];
        }
        __syncthreads();
    }
    #pragma unroll
    for (int i = 0; i < 4; i++) {
        int row = brow + threadIdx.y * 4 + i;
        if (row < M) {
            #pragma unroll
            for (int j = 0; j < 4; j++)
                C[(size_t)row * Nd + bcol + threadIdx.x * 4 + j] = acc[i][j];
        }
    }
}

// per-node attention scores: ssrc[n] = h[n,:].asrc, sdst[n] = h[n,:].adst
__global__ void scores_k(const float* __restrict__ h, const float* __restrict__ asrc,
                         const float* __restrict__ adst, int n_nodes, int D) {
    int warp = (blockIdx.x * blockDim.x + threadIdx.x) >> 5;
    int lane = threadIdx.x & 31;
    if (warp >= n_nodes) return;
    float s1 = 0.f, s2 = 0.f;
    const float* row = h + (size_t)warp * D;
    for (int d = lane; d < D; d += 32) {
        float v = row[d];
        s1 += v * asrc[d];
        s2 += v * adst[d];
    }
    #pragma unroll
    for (int o = 16; o > 0; o >>= 1) {
        s1 += __shfl_down_sync(0xFFFFFFFFu, s1, o);
        s2 += __shfl_down_sync(0xFFFFFFFFu, s2, o);
    }
    if (lane == 0) { g_ssrc[warp] = s1; g_sdst[warp] = s2; }
}

// edge pass A: leaky-relu logits + segment max over dst
__global__ void edge_logits_k(const int* __restrict__ src, const int* __restrict__ dst,
                              int E, int Et) {
    int e = blockIdx.x * blockDim.x + threadIdx.x;
    if (e >= Et) return;
    int s, d;
    if (e < E) { s = src[e]; d = dst[e]; } else { s = d = e - E; }
    float v = g_ssrc[s] + g_sdst[d];
    v = v > 0.f ? v : 0.2f * v;
    g_edge[e] = v;
    atomicMax(&g_mu[d], f2u_ord(v));
}

// edge pass B: exp(e - max) + segment sum
__global__ void edge_exp_k(const int* __restrict__ dst, int E, int Et) {
    int e = blockIdx.x * blockDim.x + threadIdx.x;
    if (e >= Et) return;
    int d = (e < E) ? dst[e] : (e - E);
    float ex = __expf(g_edge[e] - u2f_ord(g_mu[d]));
    g_edge[e] = ex;
    atomicAdd(&g_denom[d], ex);
}

// edge pass B2: alpha = ex / denom[dst]
__global__ void edge_alpha_k(const int* __restrict__ dst, int E, int Et) {
    int e = blockIdx.x * blockDim.x + threadIdx.x;
    if (e >= Et) return;
    int d = (e < E) ? dst[e] : (e - E);
    g_edge[e] = g_edge[e] / g_denom[d];
}

// edge pass C: agg[dst] += alpha * h[src]; one thread handles 4 features
__global__ void edge_agg_k(const int* __restrict__ src, const int* __restrict__ dst,
                           const float* __restrict__ h, float* __restrict__ agg,
                           int E, int Et, int D) {
    int chunks = D >> 2;
    int tid = blockIdx.x * blockDim.x + threadIdx.x;
    int e = tid / chunks;
    if (e >= Et) return;
    int c = tid - e * chunks;
    int s, d;
    if (e < E) { s = src[e]; d = dst[e]; } else { s = d = e - E; }
    float a = g_edge[e];
    float4 hv = *(const float4*)&h[(size_t)s * D + c * 4];
    float* o = &agg[(size_t)d * D + c * 4];
    atomicAdd(o + 0, hv.x * a);
    atomicAdd(o + 1, hv.y * a);
    atomicAdd(o + 2, hv.z * a);
    atomicAdd(o + 3, hv.w * a);
}

__global__ void add_bias_k(float* __restrict__ buf, const float* __restrict__ b,
                           int n_nodes, int D) {
    int idx = blockIdx.x * blockDim.x + threadIdx.x;
    if (idx >= n_nodes * D) return;
    buf[idx] += b[idx % D];
}

// graph pooling: segment max + sum + counts over batch
__global__ void pool_k(const float* __restrict__ h, const int* __restrict__ batch,
                       int n_nodes, int D) {
    int idx = blockIdx.x * blockDim.x + threadIdx.x;
    if (idx >= n_nodes * D) return;
    int n = idx / D, f = idx - n * D;
    int g = batch[n];
    float v = h[idx];
    atomicMax(&g_x1u[g * D + f], f2u_ord(v));
    atomicAdd(&g_x2[g * D + f], v);
    if (f == 0) atomicAdd(&g_cnt[g], 1.f);
}

// finalize pooling: z = [max, sum], x3 = mean
__global__ void pool_fin_k(int D) {
    int idx = blockIdx.x * blockDim.x + threadIdx.x;
    if (idx >= GG * D) return;
    int g = idx / D, f = idx - g * D;
    float mx = u2f_ord(g_x1u[idx]);
    float sm = g_x2[idx];
    g_z[g * (2 * D) + f] = mx;
    g_z[g * (2 * D) + D + f] = sm;
    g_x3[idx] = sm / fmaxf(g_cnt[g], 1.f);
}

// small dense layer: out[g,f] = act(in[g,:] @ w[:,f] + b[f]); grid=G, block=do
__global__ void dense_k(const float* __restrict__ in, const float* __restrict__ w,
                        const float* __restrict__ b, float* __restrict__ out,
                        int di, int dout, int act) {
    __shared__ float sz[512];
    int g = blockIdx.x, f = threadIdx.x;
    for (int i = f; i < di; i += blockDim.x) sz[i] = in[g * di + i];
    __syncthreads();
    float acc = b[f];
    for (int k = 0; k < di; k++) acc = fmaf(sz[k], w[k * dout + f], acc);
    if (act == 1) acc = fmaxf(acc, 0.f);
    else if (act == 2) acc = 1.f / (1.f + expf(-acc));
    out[g * dout + f] = acc;
}

__global__ void mul_k(float* __restrict__ a, const float* __restrict__ b, int n) {
    int i = blockIdx.x * blockDim.x + threadIdx.x;
    if (i < n) a[i] *= b[i];
}

// ---------------------------------------------------------------------------
static void run_gat_layer(const float* x_in, const float* W, const float* asrc,
                          const float* adst, const float* bias,
                          const int* src, const int* dst,
                          float* h_buf, float* agg_buf,
                          int n_nodes, int E, int Et, int Din, int Dout,
                          void* p_mu, void* p_denom) {
    // h = x @ W
    dim3 gblk((n_nodes + 63) / 64, Dout / 64), gthr(16, 16);
    gemm_k<<<gblk, gthr>>>(x_in, W, h_buf, n_nodes, Din, Dout);
    // scores
    scores_k<<<(n_nodes * 32 + 255) / 256, 256>>>(h_buf, asrc, adst, n_nodes, Dout);
    // clear segment buffers
    cudaMemsetAsync(p_mu, 0, n_nodes * sizeof(unsigned));
    cudaMemsetAsync(p_denom, 0, n_nodes * sizeof(float));
    cudaMemsetAsync(agg_buf, 0, (size_t)n_nodes * Dout * sizeof(float));
    // edge passes
    int tb = 256;
    edge_logits_k<<<(Et + tb - 1) / tb, tb>>>(src, dst, E, Et);
    edge_exp_k<<<(Et + tb - 1) / tb, tb>>>(dst, E, Et);
    edge_alpha_k<<<(Et + tb - 1) / tb, tb>>>(dst, E, Et);
    long long total = (long long)Et * (Dout / 4);
    edge_agg_k<<<(unsigned)((total + tb - 1) / tb), tb>>>(src, dst, h_buf, agg_buf,
                                                          E, Et, Dout);
    add_bias_k<<<(n_nodes * Dout + tb - 1) / tb, tb>>>(agg_buf, bias, n_nodes, Dout);
}

extern "C" void kernel_launch(void* const* d_in, const int* in_sizes, int n_in,
                              void* d_out, int out_size) {
    const float* x     = (const float*)d_in[0];
    const int*   eidx  = (const int*)d_in[1];
    const int*   batch = (const int*)d_in[2];
    const float* W1 = (const float*)d_in[3],  *as1 = (const float*)d_in[4],
               *ad1 = (const float*)d_in[5],  *b1  = (const float*)d_in[6];
    const float* W2 = (const float*)d_in[7],  *as2 = (const float*)d_in[8],
               *ad2 = (const float*)d_in[9],  *b2  = (const float*)d_in[10];
    const float* W3 = (const float*)d_in[11], *as3 = (const float*)d_in[12],
               *ad3 = (const float*)d_in[13], *b3  = (const float*)d_in[14];
    const float* d1w = (const float*)d_in[15], *d1b = (const float*)d_in[16];
    const float* d2w = (const float*)d_in[17], *d2b = (const float*)d_in[18];
    const float* d3w = (const float*)d_in[19], *d3b = (const float*)d_in[20];
    const float* mw  = (const float*)d_in[21], *mb  = (const float*)d_in[22];
    const float* d4w = (const float*)d_in[23], *d4b = (const float*)d_in[24];
    const float* d5w = (const float*)d_in[25], *d5b = (const float*)d_in[26];
    const float* d6w = (const float*)d_in[27], *d6b = (const float*)d_in[28];
    const float* d7w = (const float*)d_in[29], *d7b = (const float*)d_in[30];
    float* out = (float*)d_out;

    int E  = in_sizes[1] / 2;
    int n_nodes = in_sizes[2];
    int Et = E + n_nodes;
    const int* src = eidx;
    const int* dst = eidx + E;

    void *pA, *pB, *pC, *pMu, *pDen, *pX1, *pX2, *pCnt;
    cudaGetSymbolAddress(&pA, g_bufA);
    cudaGetSymbolAddress(&pB, g_bufB);
    cudaGetSymbolAddress(&pC, g_bufC);
    cudaGetSymbolAddress(&pMu, g_mu);
    cudaGetSymbolAddress(&pDen, g_denom);
    cudaGetSymbolAddress(&pX1, g_x1u);
    cudaGetSymbolAddress(&pX2, g_x2);
    cudaGetSymbolAddress(&pCnt, g_cnt);
    float* bufA = (float*)pA;
    float* bufB = (float*)pB;
    float* bufC = (float*)pC;

    // layer 1: in = x (128) -> h in bufA (64), agg -> bufB
    run_gat_layer(x, W1, as1, ad1, b1, src, dst, bufA, bufB,
                  n_nodes, E, Et, 128, 64, pMu, pDen);
    // layer 2: in = bufB (64) -> h in bufA (128), agg -> bufC
    run_gat_layer(bufB, W2, as2, ad2, b2, src, dst, bufA, bufC,
                  n_nodes, E, Et, 64, 128, pMu, pDen);
    // layer 3: in = bufC (128) -> h in bufA (256), agg -> bufB
    run_gat_layer(bufC, W3, as3, ad3, b3, src, dst, bufA, bufB,
                  n_nodes, E, Et, 128, 256, pMu, pDen);

    // pooling over batch
    cudaMemsetAsync(pX1, 0, GG * 256 * sizeof(unsigned));
    cudaMemsetAsync(pX2, 0, GG * 256 * sizeof(float));
    cudaMemsetAsync(pCnt, 0, GG * sizeof(float));
    int tb = 256;
    pool_k<<<(n_nodes * 256 + tb - 1) / tb, tb>>>(bufB, batch, n_nodes, 256);
    pool_fin_k<<<(GG * 256 + tb - 1) / tb, tb>>>(256);

    void *pz, *pt1, *pt2, *pg, *px3;
    cudaGetSymbolAddress(&pz, g_z);
    cudaGetSymbolAddress(&pt1, g_t1);
    cudaGetSymbolAddress(&pt2, g_t2);
    cudaGetSymbolAddress(&pg, g_gate);
    cudaGetSymbolAddress(&px3, g_x3);
    float* z  = (float*)pz;
    float* t1 = (float*)pt1;
    float* t2 = (float*)pt2;
    float* gt = (float*)pg;
    float* x3 = (float*)px3;

    dense_k<<<GG, 256>>>(z,  d1w, d1b, t1, 512, 256, 1);
    dense_k<<<GG, 128>>>(t1, d2w, d2b, t2, 256, 128, 1);
    dense_k<<<GG, 64>>>(t2, d3w, d3b, t1, 128, 64, 1);
    dense_k<<<GG, 64>>>(x3, mw,  mb,  gt, 256, 64, 2);
    mul_k<<<(GG * 64 + 255) / 256, 256>>>(t1, gt, GG * 64);
    dense_k<<<GG, 64>>>(t1, d4w, d4b, t2, 64, 64, 1);
    dense_k<<<GG, 128>>>(t2, d5w, d5b, t1, 64, 128, 1);
    dense_k<<<GG, 256>>>(t1, d6w, d6b, t2, 128, 256, 1);
    dense_k<<<GG, 128>>>(t2, d7w, d7b, out, 256, 128, 0);
}

// round 5
// speedup vs baseline: 2.5818x; 2.5818x over previous
#include <cuda_runtime.h>
#include <cuda_bf16.h>

// Problem constants (fixed by the dataset)
#define NN 50000
#define EE 800000
#define ET (EE + NN)   // edges + self loops
#define GG 64
#define FIN 128
#define MAXD 256

// ---------------- scratch (device globals; no allocation allowed) ----------
__device__ float    g_bufA[(size_t)NN * MAXD];
__device__ float    g_bufB[(size_t)NN * MAXD];
__device__ float    g_bufC[(size_t)NN * MAXD];
__device__ float    g_edge[ET];          // per-edge alpha
__device__ int      g_col[ET];           // CSR: src index per (dst-sorted) edge
__device__ int      g_rowptr[NN + 1];
__device__ int      g_woff[NN];
__device__ int      g_deg[NN];
__device__ int      g_bsums[256];
__device__ float    g_ssrc[NN];
__device__ float    g_sdst[NN];
__device__ unsigned g_x1u[GG * MAXD];
__device__ float    g_x2[GG * MAXD];
__device__ float    g_x3[GG * MAXD];
__device__ float    g_cnt[GG];
__device__ float    g_z[GG * 512];
__device__ float    g_t1[GG * MAXD];
__device__ float    g_t2[GG * MAXD];
__device__ float    g_gate[GG * 64];

// monotone float <-> uint mapping for atomicMax on signed floats
__device__ __forceinline__ unsigned f2u_ord(float f) {
    unsigned u = __float_as_uint(f);
    return (u & 0x80000000u) ? ~u : (u | 0x80000000u);
}
__device__ __forceinline__ float u2f_ord(unsigned u) {
    return __uint_as_float((u & 0x80000000u) ? (u & 0x7FFFFFFFu) : ~u);
}

// ======================= CSR build =========================================
__global__ void deg_init_k(int n) {
    int i = blockIdx.x * blockDim.x + threadIdx.x;
    if (i < n) g_deg[i] = 1;   // self loop
}
__global__ void hist_k(const int* __restrict__ dst, int E) {
    int e = blockIdx.x * blockDim.x + threadIdx.x;
    if (e < E) atomicAdd(&g_deg[dst[e]], 1);
}
// 3-phase exclusive scan over g_deg -> g_rowptr (block size 256)
__global__ void scan1_k(int* __restrict__ excl, int n) {
    __shared__ int s[256];
    int i = blockIdx.x * 256 + threadIdx.x;
    int v = (i < n) ? g_deg[i] : 0;
    s[threadIdx.x] = v;
    __syncthreads();
    for (int off = 1; off < 256; off <<= 1) {
        int t = (threadIdx.x >= off) ? s[threadIdx.x - off] : 0;
        __syncthreads();
        s[threadIdx.x] += t;
        __syncthreads();
    }
    if (i < n) excl[i] = s[threadIdx.x] - v;
    if (threadIdx.x == 255) g_bsums[blockIdx.x] = s[255];
}
__global__ void scan2_k(int nb) {
    __shared__ int s[256];
    int v = (threadIdx.x < nb) ? g_bsums[threadIdx.x] : 0;
    s[threadIdx.x] = v;
    __syncthreads();
    for (int off = 1; off < 256; off <<= 1) {
        int t = (threadIdx.x >= off) ? s[threadIdx.x - off] : 0;
        __syncthreads();
        s[threadIdx.x] += t;
        __syncthreads();
    }
    g_bsums[threadIdx.x] = s[threadIdx.x] - v;  // exclusive block offsets
}
__global__ void scan3_k(const int* __restrict__ excl, int n, int total) {
    int i = blockIdx.x * blockDim.x + threadIdx.x;
    if (i < n) {
        int r = excl[i] + g_bsums[i >> 8];
        g_rowptr[i] = r;
        g_woff[i] = r;
    }
    if (i == 0) g_rowptr[n] = total;
}
__global__ void scatter_k(const int* __restrict__ src, const int* __restrict__ dst,
                          int E, int Et) {
    int e = blockIdx.x * blockDim.x + threadIdx.x;
    if (e >= Et) return;
    int s, d;
    if (e < E) { s = src[e]; d = dst[e]; } else { s = d = e - E; }
    int pos = atomicAdd(&g_woff[d], 1);
    g_col[pos] = s;
}

// ---------------- tiled fp32 GEMM: C[M,Nd] = A[M,K] @ B[K,Nd] --------------
__global__ void gemm_k(const float* __restrict__ A, const float* __restrict__ B,
                       float* __restrict__ C, int M, int K, int Nd) {
    __shared__ float As[16][65];
    __shared__ float Bs[16][64];
    int tl = threadIdx.y * 16 + threadIdx.x;
    int brow = blockIdx.x * 64, bcol = blockIdx.y * 64;
    float acc[4][4] = {};
    for (int k0 = 0; k0 < K; k0 += 16) {
        int r = tl >> 2, c = (tl & 3) * 4;
        float4 av = make_float4(0.f, 0.f, 0.f, 0.f);
        if (brow + r < M)
            av = *(const float4*)&A[(size_t)(brow + r) * K + k0 + c];
        As[c + 0][r] = av.x; As[c + 1][r] = av.y;
        As[c + 2][r] = av.z; As[c + 3][r] = av.w;
        int r2 = tl >> 4, c2 = (tl & 15) * 4;
        *(float4*)&Bs[r2][c2] = *(const float4*)&B[(size_t)(k0 + r2) * Nd + bcol + c2];
        __syncthreads();
        #pragma unroll
        for (int k = 0; k < 16; k++) {
            float a[4], b[4];
            #pragma unroll
            for (int i = 0; i < 4; i++) a[i] = As[k][threadIdx.y * 4 + i];
            #pragma unroll
            for (int j = 0; j < 4; j++) b[j] = Bs[k][threadIdx.x * 4 + j];
            #pragma unroll
            for (int i = 0; i < 4; i++)
                #pragma unroll
                for (int j = 0; j < 4; j++) acc[i][j] += a[i] * b[j];
        }
        __syncthreads();
    }
    #pragma unroll
    for (int i = 0; i < 4; i++) {
        int row = brow + threadIdx.y * 4 + i;
        if (row < M) {
            #pragma unroll
            for (int j = 0; j < 4; j++)
                C[(size_t)row * Nd + bcol + threadIdx.x * 4 + j] = acc[i][j];
        }
    }
}

// per-node attention scores: ssrc[n] = h[n,:].asrc, sdst[n] = h[n,:].adst
__global__ void scores_k(const float* __restrict__ h, const float* __restrict__ asrc,
                         const float* __restrict__ adst, int n_nodes, int D) {
    int warp = (blockIdx.x * blockDim.x + threadIdx.x) >> 5;
    int lane = threadIdx.x & 31;
    if (warp >= n_nodes) return;
    float s1 = 0.f, s2 = 0.f;
    const float* row = h + (size_t)warp * D;
    for (int d = lane; d < D; d += 32) {
        float v = row[d];
        s1 += v * asrc[d];
        s2 += v * adst[d];
    }
    #pragma unroll
    for (int o = 16; o > 0; o >>= 1) {
        s1 += __shfl_down_sync(0xFFFFFFFFu, s1, o);
        s2 += __shfl_down_sync(0xFFFFFFFFu, s2, o);
    }
    if (lane == 0) { g_ssrc[warp] = s1; g_sdst[warp] = s2; }
}

// fused segment softmax: warp per dst node, CSR in-edges, writes alpha
__global__ void softmax_csr_k(int n_nodes) {
    int node = (blockIdx.x * blockDim.x + threadIdx.x) >> 5;
    int lane = threadIdx.x & 31;
    if (node >= n_nodes) return;
    int beg = g_rowptr[node], end = g_rowptr[node + 1];
    float sd = g_sdst[node];
    float m = -3.402823e38f;
    for (int j = beg + lane; j < end; j += 32) {
        float v = g_ssrc[g_col[j]] + sd;
        v = v > 0.f ? v : 0.2f * v;
        g_edge[j] = v;
        m = fmaxf(m, v);
    }
    #pragma unroll
    for (int o = 16; o > 0; o >>= 1)
        m = fmaxf(m, __shfl_xor_sync(0xFFFFFFFFu, m, o));
    float ssum = 0.f;
    for (int j = beg + lane; j < end; j += 32) {
        float ex = __expf(g_edge[j] - m);
        g_edge[j] = ex;
        ssum += ex;
    }
    #pragma unroll
    for (int o = 16; o > 0; o >>= 1)
        ssum += __shfl_xor_sync(0xFFFFFFFFu, ssum, o);
    float inv = 1.f / ssum;
    for (int j = beg + lane; j < end; j += 32)
        g_edge[j] *= inv;
}

// gather aggregation: warp per (node, 128-feature chunk); acc init = bias
__global__ void agg_csr_k(const float* __restrict__ h, const float* __restrict__ bias,
                          float* __restrict__ outbuf, int n_nodes, int D) {
    int gw = (blockIdx.x * blockDim.x + threadIdx.x) >> 5;
    int lane = threadIdx.x & 31;
    if (D >= 128) {
        int ch = D >> 7;
        int node = gw / ch;
        if (node >= n_nodes) return;
        int f = ((gw - node * ch) << 7) + lane * 4;
        float4 acc = *(const float4*)&bias[f];
        int j = g_rowptr[node], end = g_rowptr[node + 1];
        for (; j < end; j++) {
            float a = g_edge[j];
            int s = g_col[j];
            float4 hv = *(const float4*)&h[(size_t)s * D + f];
            acc.x = fmaf(a, hv.x, acc.x);
            acc.y = fmaf(a, hv.y, acc.y);
            acc.z = fmaf(a, hv.z, acc.z);
            acc.w = fmaf(a, hv.w, acc.w);
        }
        *(float4*)&outbuf[(size_t)node * D + f] = acc;
    } else {  // D == 64
        int node = gw;
        if (node >= n_nodes) return;
        int f = lane * 2;
        float2 acc = *(const float2*)&bias[f];
        int j = g_rowptr[node], end = g_rowptr[node + 1];
        for (; j < end; j++) {
            float a = g_edge[j];
            int s = g_col[j];
            float2 hv = *(const float2*)&h[(size_t)s * D + f];
            acc.x = fmaf(a, hv.x, acc.x);
            acc.y = fmaf(a, hv.y, acc.y);
        }
        *(float2*)&outbuf[(size_t)node * D + f] = acc;
    }
}

// graph pooling: batch is sorted -> block-local running reduce, flush at
// graph boundaries. block = 256 threads (one per feature), 128 nodes/block.
__global__ void pool_k(const float* __restrict__ h, const int* __restrict__ batch,
                       int n_nodes) {
    const int D = 256;
    int f = threadIdx.x;
    int n0 = blockIdx.x * 128;
    int nend = min(n0 + 128, n_nodes);
    float mx = -3.402823e38f, sm = 0.f;
    int cur = batch[n0], cnt = 0;
    for (int n = n0; n < nend; n++) {
        int g = batch[n];
        if (g != cur) {
            atomicMax(&g_x1u[cur * D + f], f2u_ord(mx));
            atomicAdd(&g_x2[cur * D + f], sm);
            if (f == 0) atomicAdd(&g_cnt[cur], (float)cnt);
            mx = -3.402823e38f; sm = 0.f; cnt = 0; cur = g;
        }
        float v = h[(size_t)n * D + f];
        mx = fmaxf(mx, v);
        sm += v;
        cnt++;
    }
    atomicMax(&g_x1u[cur * D + f], f2u_ord(mx));
    atomicAdd(&g_x2[cur * D + f], sm);
    if (f == 0) atomicAdd(&g_cnt[cur], (float)cnt);
}

// finalize pooling: z = [max, sum], x3 = mean
__global__ void pool_fin_k(int D) {
    int idx = blockIdx.x * blockDim.x + threadIdx.x;
    if (idx >= GG * D) return;
    int g = idx / D, f = idx - g * D;
    float mx = u2f_ord(g_x1u[idx]);
    float sm = g_x2[idx];
    g_z[g * (2 * D) + f] = mx;
    g_z[g * (2 * D) + D + f] = sm;
    g_x3[idx] = sm / fmaxf(g_cnt[g], 1.f);
}

// small dense layer: out[g,f] = act(in[g,:] @ w[:,f] + b[f]); grid=G, block=do
__global__ void dense_k(const float* __restrict__ in, const float* __restrict__ w,
                        const float* __restrict__ b, float* __restrict__ out,
                        int di, int dout, int act) {
    __shared__ float sz[512];
    int g = blockIdx.x, f = threadIdx.x;
    for (int i = f; i < di; i += blockDim.x) sz[i] = in[g * di + i];
    __syncthreads();
    float acc = b[f];
    for (int k = 0; k < di; k++) acc = fmaf(sz[k], w[k * dout + f], acc);
    if (act == 1) acc = fmaxf(acc, 0.f);
    else if (act == 2) acc = 1.f / (1.f + expf(-acc));
    out[g * dout + f] = acc;
}

__global__ void mul_k(float* __restrict__ a, const float* __restrict__ b, int n) {
    int i = blockIdx.x * blockDim.x + threadIdx.x;
    if (i < n) a[i] *= b[i];
}

// ---------------------------------------------------------------------------
static void run_gat_layer(const float* x_in, const float* W, const float* asrc,
                          const float* adst, const float* bias,
                          float* h_buf, float* agg_buf,
                          int n_nodes, int Din, int Dout) {
    dim3 gblk((n_nodes + 63) / 64, Dout / 64), gthr(16, 16);
    gemm_k<<<gblk, gthr>>>(x_in, W, h_buf, n_nodes, Din, Dout);
    scores_k<<<(n_nodes * 32 + 255) / 256, 256>>>(h_buf, asrc, adst, n_nodes, Dout);
    softmax_csr_k<<<(n_nodes * 32 + 255) / 256, 256>>>(n_nodes);
    int warps = (Dout >= 128) ? n_nodes * (Dout / 128) : n_nodes;
    agg_csr_k<<<(warps * 32 + 255) / 256, 256>>>(h_buf, bias, agg_buf, n_nodes, Dout);
}

extern "C" void kernel_launch(void* const* d_in, const int* in_sizes, int n_in,
                              void* d_out, int out_size) {
    const float* x     = (const float*)d_in[0];
    const int*   eidx  = (const int*)d_in[1];
    const int*   batch = (const int*)d_in[2];
    const float* W1 = (const float*)d_in[3],  *as1 = (const float*)d_in[4],
               *ad1 = (const float*)d_in[5],  *b1  = (const float*)d_in[6];
    const float* W2 = (const float*)d_in[7],  *as2 = (const float*)d_in[8],
               *ad2 = (const float*)d_in[9],  *b2  = (const float*)d_in[10];
    const float* W3 = (const float*)d_in[11], *as3 = (const float*)d_in[12],
               *ad3 = (const float*)d_in[13], *b3  = (const float*)d_in[14];
    const float* d1w = (const float*)d_in[15], *d1b = (const float*)d_in[16];
    const float* d2w = (const float*)d_in[17], *d2b = (const float*)d_in[18];
    const float* d3w = (const float*)d_in[19], *d3b = (const float*)d_in[20];
    const float* mw  = (const float*)d_in[21], *mb  = (const float*)d_in[22];
    const float* d4w = (const float*)d_in[23], *d4b = (const float*)d_in[24];
    const float* d5w = (const float*)d_in[25], *d5b = (const float*)d_in[26];
    const float* d6w = (const float*)d_in[27], *d6b = (const float*)d_in[28];
    const float* d7w = (const float*)d_in[29], *d7b = (const float*)d_in[30];
    float* out = (float*)d_out;

    int E  = in_sizes[1] / 2;
    int n_nodes = in_sizes[2];
    int Et = E + n_nodes;
    const int* src = eidx;
    const int* dst = eidx + E;

    void *pA, *pB, *pC, *pX1, *pX2, *pCnt, *pExcl;
    cudaGetSymbolAddress(&pA, g_bufA);
    cudaGetSymbolAddress(&pB, g_bufB);
    cudaGetSymbolAddress(&pC, g_bufC);
    cudaGetSymbolAddress(&pX1, g_x1u);
    cudaGetSymbolAddress(&pX2, g_x2);
    cudaGetSymbolAddress(&pCnt, g_cnt);
    cudaGetSymbolAddress(&pExcl, g_bufA);  // reuse bufA head as scan scratch
    float* bufA = (float*)pA;
    float* bufB = (float*)pB;
    float* bufC = (float*)pC;
    int* excl = (int*)pExcl;

    // ---- CSR build (dst-sorted, with self-loops appended per node) ----
    int tb = 256;
    deg_init_k<<<(n_nodes + tb - 1) / tb, tb>>>(n_nodes);
    hist_k<<<(E + tb - 1) / tb, tb>>>(dst, E);
    int nblk = (n_nodes + 255) / 256;
    scan1_k<<<nblk, 256>>>(excl, n_nodes);
    scan2_k<<<1, 256>>>(nblk);
    scan3_k<<<nblk, 256>>>(excl, n_nodes, Et);
    scatter_k<<<(Et + tb - 1) / tb, tb>>>(src, dst, E, Et);

    // layer 1: x(128) -> h bufA(64), agg -> bufB
    run_gat_layer(x, W1, as1, ad1, b1, bufA, bufB, n_nodes, 128, 64);
    // layer 2: bufB(64) -> h bufA(128), agg -> bufC
    run_gat_layer(bufB, W2, as2, ad2, b2, bufA, bufC, n_nodes, 64, 128);
    // layer 3: bufC(128) -> h bufA(256), agg -> bufB
    run_gat_layer(bufC, W3, as3, ad3, b3, bufA, bufB, n_nodes, 128, 256);

    // pooling over batch (sorted)
    cudaMemsetAsync(pX1, 0, GG * 256 * sizeof(unsigned));
    cudaMemsetAsync(pX2, 0, GG * 256 * sizeof(float));
    cudaMemsetAsync(pCnt, 0, GG * sizeof(float));
    pool_k<<<(n_nodes + 127) / 128, 256>>>(bufB, batch, n_nodes);
    pool_fin_k<<<(GG * 256 + tb - 1) / tb, tb>>>(256);

    void *pz, *pt1, *pt2, *pg, *px3;
    cudaGetSymbolAddress(&pz, g_z);
    cudaGetSymbolAddress(&pt1, g_t1);
    cudaGetSymbolAddress(&pt2, g_t2);
    cudaGetSymbolAddress(&pg, g_gate);
    cudaGetSymbolAddress(&px3, g_x3);
    float* z  = (float*)pz;
    float* t1 = (float*)pt1;
    float* t2 = (float*)pt2;
    float* gt = (float*)pg;
    float* x3 = (float*)px3;

    dense_k<<<GG, 256>>>(z,  d1w, d1b, t1, 512, 256, 1);
    dense_k<<<GG, 128>>>(t1, d2w, d2b, t2, 256, 128, 1);
    dense_k<<<GG, 64>>>(t2, d3w, d3b, t1, 128, 64, 1);
    dense_k<<<GG, 64>>>(x3, mw,  mb,  gt, 256, 64, 2);
    mul_k<<<(GG * 64 + 255) / 256, 256>>>(t1, gt, GG * 64);
    dense_k<<<GG, 64>>>(t1, d4w, d4b, t2, 64, 64, 1);
    dense_k<<<GG, 128>>>(t2, d5w, d5b, t1, 64, 128, 1);
    dense_k<<<GG, 256>>>(t1, d6w, d6b, t2, 128, 256, 1);
    dense_k<<<GG, 128>>>(t2, d7w, d7b, out, 256, 128, 0);
}

// round 6
// speedup vs baseline: 2.8663x; 1.1102x over previous
#include <cuda_runtime.h>
#include <cuda_bf16.h>

// Problem constants (fixed by the dataset)
#define NN 50000
#define EE 800000
#define ET (EE + NN)   // edges + self loops
#define GG 64
#define FIN 128
#define MAXD 256

// ---------------- scratch (device globals; no allocation allowed) ----------
__device__ float    g_bufA[(size_t)NN * MAXD];
__device__ float    g_bufB[(size_t)NN * MAXD];
__device__ float    g_bufC[(size_t)NN * MAXD];
__device__ float    g_edge[ET];          // per-edge alpha
__device__ int      g_col[ET];           // CSR: src index per (dst-sorted) edge
__device__ int      g_rowptr[NN + 1];
__device__ int      g_woff[NN];
__device__ int      g_deg[NN];
__device__ int      g_bsums[256];
__device__ float    g_ssrc[NN];
__device__ float    g_sdst[NN];
__device__ unsigned g_x1u[GG * MAXD];
__device__ float    g_x2[GG * MAXD];
__device__ float    g_cnt[GG];

// monotone float <-> uint mapping for atomicMax on signed floats
__device__ __forceinline__ unsigned f2u_ord(float f) {
    unsigned u = __float_as_uint(f);
    return (u & 0x80000000u) ? ~u : (u | 0x80000000u);
}
__device__ __forceinline__ float u2f_ord(unsigned u) {
    return __uint_as_float((u & 0x80000000u) ? (u & 0x7FFFFFFFu) : ~u);
}

// ======================= CSR build =========================================
__global__ void deg_init_k(int n) {
    int i = blockIdx.x * blockDim.x + threadIdx.x;
    if (i < n) g_deg[i] = 1;   // self loop
}
__global__ void hist_k(const int* __restrict__ dst, int E) {
    int e = blockIdx.x * blockDim.x + threadIdx.x;
    if (e < E) atomicAdd(&g_deg[dst[e]], 1);
}
// 3-phase exclusive scan over g_deg -> g_rowptr (block size 256)
__global__ void scan1_k(int* __restrict__ excl, int n) {
    __shared__ int s[256];
    int i = blockIdx.x * 256 + threadIdx.x;
    int v = (i < n) ? g_deg[i] : 0;
    s[threadIdx.x] = v;
    __syncthreads();
    for (int off = 1; off < 256; off <<= 1) {
        int t = (threadIdx.x >= off) ? s[threadIdx.x - off] : 0;
        __syncthreads();
        s[threadIdx.x] += t;
        __syncthreads();
    }
    if (i < n) excl[i] = s[threadIdx.x] - v;
    if (threadIdx.x == 255) g_bsums[blockIdx.x] = s[255];
}
__global__ void scan2_k(int nb) {
    __shared__ int s[256];
    int v = (threadIdx.x < nb) ? g_bsums[threadIdx.x] : 0;
    s[threadIdx.x] = v;
    __syncthreads();
    for (int off = 1; off < 256; off <<= 1) {
        int t = (threadIdx.x >= off) ? s[threadIdx.x - off] : 0;
        __syncthreads();
        s[threadIdx.x] += t;
        __syncthreads();
    }
    g_bsums[threadIdx.x] = s[threadIdx.x] - v;  // exclusive block offsets
}
__global__ void scan3_k(const int* __restrict__ excl, int n, int total) {
    int i = blockIdx.x * blockDim.x + threadIdx.x;
    if (i < n) {
        int r = excl[i] + g_bsums[i >> 8];
        g_rowptr[i] = r;
        g_woff[i] = r;
    }
    if (i == 0) g_rowptr[n] = total;
}
__global__ void scatter_k(const int* __restrict__ src, const int* __restrict__ dst,
                          int E, int Et) {
    int e = blockIdx.x * blockDim.x + threadIdx.x;
    if (e >= Et) return;
    int s, d;
    if (e < E) { s = src[e]; d = dst[e]; } else { s = d = e - E; }
    int pos = atomicAdd(&g_woff[d], 1);
    g_col[pos] = s;
}

// ---------------- tiled fp32 GEMM: C[M,Nd] = A[M,K] @ B[K,Nd] --------------
// BM=128, BN=64, BK=16; 256 threads; 8x4 micro-tile per thread.
// Requires K % 16 == 0, Nd % 64 == 0. M guarded.
__global__ void gemm_k(const float* __restrict__ A, const float* __restrict__ B,
                       float* __restrict__ C, int M, int K, int Nd) {
    __shared__ float As[16][132];   // [k][row], pad 132 (528B rows, 16B aligned)
    __shared__ float Bs[16][64];    // [k][col]
    int brow = blockIdx.x * 128, bcol = blockIdx.y * 64;
    int tid = threadIdx.x;
    int ty = tid >> 4;          // 0..15 -> rows ty*8 .. ty*8+7
    int tx = tid & 15;          // 0..15 -> cols tx*4 .. tx*4+3
    float acc[8][4] = {};
    for (int k0 = 0; k0 < K; k0 += 16) {
        // A tile: 128x16 = 512 float4 loads; 2 per thread
        #pragma unroll
        for (int l = 0; l < 2; l++) {
            int idx = tid + l * 256;          // 0..511
            int r = idx >> 2;                 // 0..127
            int c = (idx & 3) * 4;            // 0,4,8,12
            float4 v = make_float4(0.f, 0.f, 0.f, 0.f);
            if (brow + r < M)
                v = *(const float4*)&A[(size_t)(brow + r) * K + k0 + c];
            As[c + 0][r] = v.x; As[c + 1][r] = v.y;
            As[c + 2][r] = v.z; As[c + 3][r] = v.w;
        }
        // B tile: 16x64 = 256 float4 loads; 1 per thread
        {
            int r = tid >> 4;                 // 0..15
            int c = (tid & 15) * 4;
            *(float4*)&Bs[r][c] = *(const float4*)&B[(size_t)(k0 + r) * Nd + bcol + c];
        }
        __syncthreads();
        #pragma unroll
        for (int k = 0; k < 16; k++) {
            float4 a0 = *(const float4*)&As[k][ty * 8];
            float4 a1 = *(const float4*)&As[k][ty * 8 + 4];
            float4 bv = *(const float4*)&Bs[k][tx * 4];
            float a[8] = {a0.x, a0.y, a0.z, a0.w, a1.x, a1.y, a1.z, a1.w};
            float b[4] = {bv.x, bv.y, bv.z, bv.w};
            #pragma unroll
            for (int i = 0; i < 8; i++)
                #pragma unroll
                for (int j = 0; j < 4; j++)
                    acc[i][j] = fmaf(a[i], b[j], acc[i][j]);
        }
        __syncthreads();
    }
    #pragma unroll
    for (int i = 0; i < 8; i++) {
        int row = brow + ty * 8 + i;
        if (row < M) {
            float4 v = make_float4(acc[i][0], acc[i][1], acc[i][2], acc[i][3]);
            *(float4*)&C[(size_t)row * Nd + bcol + tx * 4] = v;
        }
    }
}

// per-node attention scores: ssrc[n] = h[n,:].asrc, sdst[n] = h[n,:].adst
__global__ void scores_k(const float* __restrict__ h, const float* __restrict__ asrc,
                         const float* __restrict__ adst, int n_nodes, int D) {
    int warp = (blockIdx.x * blockDim.x + threadIdx.x) >> 5;
    int lane = threadIdx.x & 31;
    if (warp >= n_nodes) return;
    float s1 = 0.f, s2 = 0.f;
    const float* row = h + (size_t)warp * D;
    for (int d = lane; d < D; d += 32) {
        float v = row[d];
        s1 += v * asrc[d];
        s2 += v * adst[d];
    }
    #pragma unroll
    for (int o = 16; o > 0; o >>= 1) {
        s1 += __shfl_down_sync(0xFFFFFFFFu, s1, o);
        s2 += __shfl_down_sync(0xFFFFFFFFu, s2, o);
    }
    if (lane == 0) { g_ssrc[warp] = s1; g_sdst[warp] = s2; }
}

// fused segment softmax: warp per dst node, CSR in-edges, writes alpha
__global__ void softmax_csr_k(int n_nodes) {
    int node = (blockIdx.x * blockDim.x + threadIdx.x) >> 5;
    int lane = threadIdx.x & 31;
    if (node >= n_nodes) return;
    int beg = g_rowptr[node], end = g_rowptr[node + 1];
    float sd = g_sdst[node];
    float m = -3.402823e38f;
    for (int j = beg + lane; j < end; j += 32) {
        float v = g_ssrc[g_col[j]] + sd;
        v = v > 0.f ? v : 0.2f * v;
        g_edge[j] = v;
        m = fmaxf(m, v);
    }
    #pragma unroll
    for (int o = 16; o > 0; o >>= 1)
        m = fmaxf(m, __shfl_xor_sync(0xFFFFFFFFu, m, o));
    float ssum = 0.f;
    for (int j = beg + lane; j < end; j += 32) {
        float ex = __expf(g_edge[j] - m);
        g_edge[j] = ex;
        ssum += ex;
    }
    #pragma unroll
    for (int o = 16; o > 0; o >>= 1)
        ssum += __shfl_xor_sync(0xFFFFFFFFu, ssum, o);
    float inv = 1.f / ssum;
    for (int j = beg + lane; j < end; j += 32)
        g_edge[j] *= inv;
}

// gather aggregation: warp per (node, 128-feature chunk); acc init = bias
__global__ void agg_csr_k(const float* __restrict__ h, const float* __restrict__ bias,
                          float* __restrict__ outbuf, int n_nodes, int D) {
    int gw = (blockIdx.x * blockDim.x + threadIdx.x) >> 5;
    int lane = threadIdx.x & 31;
    if (D >= 128) {
        int ch = D >> 7;
        int node = gw / ch;
        if (node >= n_nodes) return;
        int f = ((gw - node * ch) << 7) + lane * 4;
        float4 acc = *(const float4*)&bias[f];
        int j = g_rowptr[node], end = g_rowptr[node + 1];
        for (; j < end; j++) {
            float a = g_edge[j];
            int s = g_col[j];
            float4 hv = *(const float4*)&h[(size_t)s * D + f];
            acc.x = fmaf(a, hv.x, acc.x);
            acc.y = fmaf(a, hv.y, acc.y);
            acc.z = fmaf(a, hv.z, acc.z);
            acc.w = fmaf(a, hv.w, acc.w);
        }
        *(float4*)&outbuf[(size_t)node * D + f] = acc;
    } else {  // D == 64
        int node = gw;
        if (node >= n_nodes) return;
        int f = lane * 2;
        float2 acc = *(const float2*)&bias[f];
        int j = g_rowptr[node], end = g_rowptr[node + 1];
        for (; j < end; j++) {
            float a = g_edge[j];
            int s = g_col[j];
            float2 hv = *(const float2*)&h[(size_t)s * D + f];
            acc.x = fmaf(a, hv.x, acc.x);
            acc.y = fmaf(a, hv.y, acc.y);
        }
        *(float2*)&outbuf[(size_t)node * D + f] = acc;
    }
}

// graph pooling: batch is sorted -> block-local running reduce, flush at
// graph boundaries. block = 256 threads (one per feature), 128 nodes/block.
__global__ void pool_k(const float* __restrict__ h, const int* __restrict__ batch,
                       int n_nodes) {
    const int D = 256;
    int f = threadIdx.x;
    int n0 = blockIdx.x * 128;
    int nend = min(n0 + 128, n_nodes);
    float mx = -3.402823e38f, sm = 0.f;
    int cur = batch[n0], cnt = 0;
    for (int n = n0; n < nend; n++) {
        int g = batch[n];
        if (g != cur) {
            atomicMax(&g_x1u[cur * D + f], f2u_ord(mx));
            atomicAdd(&g_x2[cur * D + f], sm);
            if (f == 0) atomicAdd(&g_cnt[cur], (float)cnt);
            mx = -3.402823e38f; sm = 0.f; cnt = 0; cur = g;
        }
        float v = h[(size_t)n * D + f];
        mx = fmaxf(mx, v);
        sm += v;
        cnt++;
    }
    atomicMax(&g_x1u[cur * D + f], f2u_ord(mx));
    atomicAdd(&g_x2[cur * D + f], sm);
    if (f == 0) atomicAdd(&g_cnt[cur], (float)cnt);
}

// ---------------- fused dense tail: one block per graph --------------------
// smem dense layer: out_s[f] = act(in_s[:] . w[:,f] + b[f])
__device__ __forceinline__ void dense_s(const float* __restrict__ in_s,
                                        const float* __restrict__ w,
                                        const float* __restrict__ b,
                                        float* __restrict__ out_s,
                                        int di, int dout, int act, int f) {
    if (f < dout) {
        float a0 = b[f], a1 = 0.f, a2 = 0.f, a3 = 0.f;
        for (int k = 0; k < di; k += 4) {
            a0 = fmaf(in_s[k + 0], w[(k + 0) * dout + f], a0);
            a1 = fmaf(in_s[k + 1], w[(k + 1) * dout + f], a1);
            a2 = fmaf(in_s[k + 2], w[(k + 2) * dout + f], a2);
            a3 = fmaf(in_s[k + 3], w[(k + 3) * dout + f], a3);
        }
        float acc = (a0 + a1) + (a2 + a3);
        if (act == 1) acc = fmaxf(acc, 0.f);
        else if (act == 2) acc = 1.f / (1.f + expf(-acc));
        out_s[f] = acc;
    }
}

__global__ void tail_k(const float* __restrict__ d1w, const float* __restrict__ d1b,
                       const float* __restrict__ d2w, const float* __restrict__ d2b,
                       const float* __restrict__ d3w, const float* __restrict__ d3b,
                       const float* __restrict__ mw,  const float* __restrict__ mb,
                       const float* __restrict__ d4w, const float* __restrict__ d4b,
                       const float* __restrict__ d5w, const float* __restrict__ d5b,
                       const float* __restrict__ d6w, const float* __restrict__ d6b,
                       const float* __restrict__ d7w, const float* __restrict__ d7b,
                       float* __restrict__ out) {
    __shared__ float z[512], x3s[256], bufA[256], bufB[256], gate[64];
    int g = blockIdx.x, f = threadIdx.x;   // 256 threads
    // pool finalize for this graph
    {
        int idx = g * 256 + f;
        float sm = g_x2[idx];
        z[f] = u2f_ord(g_x1u[idx]);
        z[256 + f] = sm;
        x3s[f] = sm / fmaxf(g_cnt[g], 1.f);
    }
    __syncthreads();
    dense_s(z,    d1w, d1b, bufA, 512, 256, 1, f);  __syncthreads();
    dense_s(bufA, d2w, d2b, bufB, 256, 128, 1, f);  __syncthreads();
    dense_s(bufB, d3w, d3b, bufA, 128, 64, 1, f);
    dense_s(x3s,  mw,  mb,  gate, 256, 64, 2, f);   __syncthreads();
    if (f < 64) bufA[f] *= gate[f];                 __syncthreads();
    dense_s(bufA, d4w, d4b, bufB, 64, 64, 1, f);    __syncthreads();
    dense_s(bufB, d5w, d5b, bufA, 64, 128, 1, f);   __syncthreads();
    dense_s(bufA, d6w, d6b, bufB, 128, 256, 1, f);  __syncthreads();
    if (f < 128) {
        float a0 = d7b[f], a1 = 0.f, a2 = 0.f, a3 = 0.f;
        for (int k = 0; k < 256; k += 4) {
            a0 = fmaf(bufB[k + 0], d7w[(k + 0) * 128 + f], a0);
            a1 = fmaf(bufB[k + 1], d7w[(k + 1) * 128 + f], a1);
            a2 = fmaf(bufB[k + 2], d7w[(k + 2) * 128 + f], a2);
            a3 = fmaf(bufB[k + 3], d7w[(k + 3) * 128 + f], a3);
        }
        out[g * 128 + f] = (a0 + a1) + (a2 + a3);
    }
}

// ---------------------------------------------------------------------------
static void run_gat_layer(const float* x_in, const float* W, const float* asrc,
                          const float* adst, const float* bias,
                          float* h_buf, float* agg_buf,
                          int n_nodes, int Din, int Dout) {
    dim3 gblk((n_nodes + 127) / 128, Dout / 64);
    gemm_k<<<gblk, 256>>>(x_in, W, h_buf, n_nodes, Din, Dout);
    scores_k<<<(n_nodes * 32 + 255) / 256, 256>>>(h_buf, asrc, adst, n_nodes, Dout);
    softmax_csr_k<<<(n_nodes * 32 + 255) / 256, 256>>>(n_nodes);
    int warps = (Dout >= 128) ? n_nodes * (Dout / 128) : n_nodes;
    agg_csr_k<<<(warps * 32 + 255) / 256, 256>>>(h_buf, bias, agg_buf, n_nodes, Dout);
}

extern "C" void kernel_launch(void* const* d_in, const int* in_sizes, int n_in,
                              void* d_out, int out_size) {
    const float* x     = (const float*)d_in[0];
    const int*   eidx  = (const int*)d_in[1];
    const int*   batch = (const int*)d_in[2];
    const float* W1 = (const float*)d_in[3],  *as1 = (const float*)d_in[4],
               *ad1 = (const float*)d_in[5],  *b1  = (const float*)d_in[6];
    const float* W2 = (const float*)d_in[7],  *as2 = (const float*)d_in[8],
               *ad2 = (const float*)d_in[9],  *b2  = (const float*)d_in[10];
    const float* W3 = (const float*)d_in[11], *as3 = (const float*)d_in[12],
               *ad3 = (const float*)d_in[13], *b3  = (const float*)d_in[14];
    const float* d1w = (const float*)d_in[15], *d1b = (const float*)d_in[16];
    const float* d2w = (const float*)d_in[17], *d2b = (const float*)d_in[18];
    const float* d3w = (const float*)d_in[19], *d3b = (const float*)d_in[20];
    const float* mw  = (const float*)d_in[21], *mb  = (const float*)d_in[22];
    const float* d4w = (const float*)d_in[23], *d4b = (const float*)d_in[24];
    const float* d5w = (const float*)d_in[25], *d5b = (const float*)d_in[26];
    const float* d6w = (const float*)d_in[27], *d6b = (const float*)d_in[28];
    const float* d7w = (const float*)d_in[29], *d7b = (const float*)d_in[30];
    float* out = (float*)d_out;

    int E  = in_sizes[1] / 2;
    int n_nodes = in_sizes[2];
    int Et = E + n_nodes;
    const int* src = eidx;
    const int* dst = eidx + E;

    void *pA, *pB, *pC, *pX1, *pX2, *pCnt;
    cudaGetSymbolAddress(&pA, g_bufA);
    cudaGetSymbolAddress(&pB, g_bufB);
    cudaGetSymbolAddress(&pC, g_bufC);
    cudaGetSymbolAddress(&pX1, g_x1u);
    cudaGetSymbolAddress(&pX2, g_x2);
    cudaGetSymbolAddress(&pCnt, g_cnt);
    float* bufA = (float*)pA;
    float* bufB = (float*)pB;
    float* bufC = (float*)pC;
    int* excl = (int*)pA;   // reuse bufA head as scan scratch (pre-layer1)

    // ---- CSR build (dst-sorted, with self-loops appended per node) ----
    int tb = 256;
    deg_init_k<<<(n_nodes + tb - 1) / tb, tb>>>(n_nodes);
    hist_k<<<(E + tb - 1) / tb, tb>>>(dst, E);
    int nblk = (n_nodes + 255) / 256;
    scan1_k<<<nblk, 256>>>(excl, n_nodes);
    scan2_k<<<1, 256>>>(nblk);
    scan3_k<<<nblk, 256>>>(excl, n_nodes, Et);
    scatter_k<<<(Et + tb - 1) / tb, tb>>>(src, dst, E, Et);

    // layer 1: x(128) -> h bufA(64), agg -> bufB
    run_gat_layer(x, W1, as1, ad1, b1, bufA, bufB, n_nodes, 128, 64);
    // layer 2: bufB(64) -> h bufA(128), agg -> bufC
    run_gat_layer(bufB, W2, as2, ad2, b2, bufA, bufC, n_nodes, 64, 128);
    // layer 3: bufC(128) -> h bufA(256), agg -> bufB
    run_gat_layer(bufC, W3, as3, ad3, b3, bufA, bufB, n_nodes, 128, 256);

    // pooling over batch (sorted)
    cudaMemsetAsync(pX1, 0, GG * 256 * sizeof(unsigned));
    cudaMemsetAsync(pX2, 0, GG * 256 * sizeof(float));
    cudaMemsetAsync(pCnt, 0, GG * sizeof(float));
    pool_k<<<(n_nodes + 127) / 128, 256>>>(bufB, batch, n_nodes);

    // fused pool-finalize + dense tail (one block per graph)
    tail_k<<<GG, 256>>>(d1w, d1b, d2w, d2b, d3w, d3b, mw, mb,
                        d4w, d4b, d5w, d5b, d6w, d6b, d7w, d7b, out);
}